// round 9
// baseline (speedup 1.0000x reference)
#include <cuda_runtime.h>
#include <cuda_bf16.h>

// TimeFeatureEmbedding: y = x @ W^T + b  ([B,T,4] x [512,4] -> [B,T,512]),
// broadcast each (b,t) row S times -> [B,T,S,512].  402.7 MB pure store stream.
//
// History: R2 1-CTA/row 61.5us; R5 persistent REGRESSED (straggler-bound);
// R6 split=2 59.9us; R7 split=4 57.8us (7.17 TB/s effective). This round:
// split=8 -> grid 24576, 4 STG.128/thread -> halve the end-of-kernel drain
// ramp once more. Slice bases/lengths remain multiples of the 256-float4
// CTA stride, so each thread's D-slice (tid & 127) is one register-resident
// float4 and every warp store is 512B contiguous. Split passed as a shift
// to avoid per-CTA integer division.

__global__ __launch_bounds__(256, 8)
void tfe_broadcast_kernel(const float* __restrict__ x,
                          const float* __restrict__ W,
                          const float* __restrict__ b,
                          float* __restrict__ out,
                          int S, int split_shift)
{
    const int bt   = blockIdx.x >> split_shift;              // (b,t) row
    const int part = blockIdx.x & ((1 << split_shift) - 1);  // slice of S repeats
    const int tid  = threadIdx.x;
    const int d4   = tid & 127;              // float4 index within D_MODEL=512

    // x row: 4 floats broadcast across the CTA (L2-hot after first touch)
    const float4 x4 = __ldg(reinterpret_cast<const float4*>(x) + bt);

    // bias + W slice for this thread's 4 output dims
    const float4 b4 = __ldg(reinterpret_cast<const float4*>(b) + d4);
    const float4* W4 = reinterpret_cast<const float4*>(W);
    const float4 w0 = __ldg(W4 + d4 * 4 + 0);
    const float4 w1 = __ldg(W4 + d4 * 4 + 1);
    const float4 w2 = __ldg(W4 + d4 * 4 + 2);
    const float4 w3 = __ldg(W4 + d4 * 4 + 3);

    float4 y4;
    y4.x = fmaf(x4.x, w0.x, fmaf(x4.y, w0.y, fmaf(x4.z, w0.z, fmaf(x4.w, w0.w, b4.x))));
    y4.y = fmaf(x4.x, w1.x, fmaf(x4.y, w1.y, fmaf(x4.z, w1.z, fmaf(x4.w, w1.w, b4.y))));
    y4.z = fmaf(x4.x, w2.x, fmaf(x4.y, w2.y, fmaf(x4.z, w2.z, fmaf(x4.w, w2.w, b4.z))));
    y4.w = fmaf(x4.x, w3.x, fmaf(x4.y, w3.y, fmaf(x4.z, w3.z, fmaf(x4.w, w3.w, b4.w))));

    // Slice: (S >> split_shift) * 128 float4, contiguous, 256-aligned start.
    // Launcher guarantees S >> split_shift is even -> slice length is a
    // multiple of 256 -> (i & 127) == d4 every iteration: one register
    // streamed, warps write 512B contiguous per STG.
    const int slice4 = (S >> split_shift) * 128;
    float4* out4 = reinterpret_cast<float4*>(out)
                 + (size_t)bt * (size_t)S * 128u
                 + (size_t)part * (size_t)slice4;

    #pragma unroll 4
    for (int i = tid; i < slice4; i += 256) {
        __stcs(out4 + i, y4);   // evict-first streaming store
    }
}

extern "C" void kernel_launch(void* const* d_in, const int* in_sizes, int n_in,
                              void* d_out, int out_size)
{
    // Inputs: x [B,T,4] f32, S (scalar), W [512,4] f32, b [512] f32.
    const float* x = (const float*)d_in[0];
    const float* W = (const float*)d_in[2];
    const float* b = (const float*)d_in[3];
    float* out = (float*)d_out;

    const int BT = in_sizes[0] / 4;          // B*T rows (d_inp = 4)
    const int S  = out_size / (BT * 512);    // recover S arithmetically

    // Largest split_shift in {3,2,1,0} keeping S/split even (preserves the
    // 256-float4 alignment invariant). S=64 -> shift=3 (split=8), grid=24576,
    // 4 stores/thread.
    int shift = 0;
    if      ((S % 16) == 0) shift = 3;
    else if ((S %  8) == 0) shift = 2;
    else if ((S %  4) == 0) shift = 1;

    tfe_broadcast_kernel<<<BT << shift, 256>>>(x, W, b, out, S, shift);
}

// round 10
// speedup vs baseline: 1.2192x; 1.2192x over previous
#include <cuda_runtime.h>
#include <cuda_bf16.h>

// TimeFeatureEmbedding: y = x @ W^T + b  ([B,T,4] x [512,4] -> [B,T,512]),
// broadcast each (b,t) row S times -> [B,T,S,512].  402.7 MB pure store stream.
//
// History: R2 61.5us; R5 persistent REGRESSED; R6 split=2 59.9us; R7 split=4
// 57.8us (7.17 TB/s eff); R8 split=8/256thr REGRESSED to 75.8us — L1 84%:
// 256-thread CTAs load W/b redundantly (t and t+128 duplicate), and doubling
// CTA count made prologue-load wavefronts the binding L1 pipe.
//
// This round: split=8 with 128-THREAD CTAs. d4 = tid -> zero redundant W/b
// loads; total load-wavefront traffic equals R7's (where L1 was 71.6%), but
// scheduling granularity is 2x finer -> smaller end-of-kernel drain ramp.
// 8 STG.128/thread, warp stores 512B contiguous, slice length (1024 float4)
// a multiple of the 128-float4 CTA stride so (i & 127) == tid always.

__global__ __launch_bounds__(128)
void tfe_broadcast_kernel(const float* __restrict__ x,
                          const float* __restrict__ W,
                          const float* __restrict__ b,
                          float* __restrict__ out,
                          int S, int split_shift)
{
    const int bt   = blockIdx.x >> split_shift;              // (b,t) row
    const int part = blockIdx.x & ((1 << split_shift) - 1);  // slice of S repeats
    const int d4   = threadIdx.x;            // float4 index within D_MODEL=512

    // x row: 4 floats broadcast across the CTA (L2/L1-hot after first touch)
    const float4 x4 = __ldg(reinterpret_cast<const float4*>(x) + bt);

    // bias + W slice for this thread's 4 output dims (unique per thread)
    const float4 b4 = __ldg(reinterpret_cast<const float4*>(b) + d4);
    const float4* W4 = reinterpret_cast<const float4*>(W);
    const float4 w0 = __ldg(W4 + d4 * 4 + 0);
    const float4 w1 = __ldg(W4 + d4 * 4 + 1);
    const float4 w2 = __ldg(W4 + d4 * 4 + 2);
    const float4 w3 = __ldg(W4 + d4 * 4 + 3);

    float4 y4;
    y4.x = fmaf(x4.x, w0.x, fmaf(x4.y, w0.y, fmaf(x4.z, w0.z, fmaf(x4.w, w0.w, b4.x))));
    y4.y = fmaf(x4.x, w1.x, fmaf(x4.y, w1.y, fmaf(x4.z, w1.z, fmaf(x4.w, w1.w, b4.y))));
    y4.z = fmaf(x4.x, w2.x, fmaf(x4.y, w2.y, fmaf(x4.z, w2.z, fmaf(x4.w, w2.w, b4.z))));
    y4.w = fmaf(x4.x, w3.x, fmaf(x4.y, w3.y, fmaf(x4.z, w3.z, fmaf(x4.w, w3.w, b4.w))));

    // Slice: (S >> split_shift) * 128 float4, contiguous, 128-aligned start.
    // Stride 128 == D_MODEL/4 -> (i & 127) == d4 on every iteration: one
    // register-resident float4 streamed; each warp store is 512B contiguous.
    const int slice4 = (S >> split_shift) * 128;
    float4* out4 = reinterpret_cast<float4*>(out)
                 + (size_t)bt * (size_t)S * 128u
                 + (size_t)part * (size_t)slice4;

    #pragma unroll 8
    for (int i = d4; i < slice4; i += 128) {
        __stcs(out4 + i, y4);   // evict-first streaming store
    }
}

extern "C" void kernel_launch(void* const* d_in, const int* in_sizes, int n_in,
                              void* d_out, int out_size)
{
    // Inputs: x [B,T,4] f32, S (scalar), W [512,4] f32, b [512] f32.
    const float* x = (const float*)d_in[0];
    const float* W = (const float*)d_in[2];
    const float* b = (const float*)d_in[3];
    float* out = (float*)d_out;

    const int BT = in_sizes[0] / 4;          // B*T rows (d_inp = 4)
    const int S  = out_size / (BT * 512);    // recover S arithmetically

    // Largest split_shift in {3,2,1,0} with S >> shift >= 1 (any S/split >= 1
    // keeps the slice a multiple of the 128-float4 stride). S=64 -> shift=3:
    // grid 24576, 8 stores/thread.
    int shift = 0;
    if      ((S % 8) == 0) shift = 3;
    else if ((S % 4) == 0) shift = 2;
    else if ((S % 2) == 0) shift = 1;

    tfe_broadcast_kernel<<<BT << shift, 128>>>(x, W, b, out, S, shift);
}

// round 11
// speedup vs baseline: 1.2449x; 1.0210x over previous
#include <cuda_runtime.h>
#include <cuda_bf16.h>

// TimeFeatureEmbedding: y = x @ W^T + b  ([B,T,4] x [512,4] -> [B,T,512]),
// broadcast each (b,t) row S times -> [B,T,S,512].  402.7 MB pure store stream.
//
// History: R2 61.5; R5 persistent REGR; R6 split2 59.9; R7 split4/256thr 57.8
// (optimum schedule); R8 split8/256thr REGR 75.8 (L1 load wavefronts);
// R9 split8/128thr REGR 62.2 (same loads/stores as R7 -> extra CTAs only add
// prologue exposure). Conclusion: R7's grid shape is optimal; the remaining
// waste is each CTA regenerating y from 20KB of W/b loads (245MB total) via
// a long dependent chain.
//
// This round: two-phase. K1 materializes Y[BT,512] (6.3MB, L2-resident) in a
// __device__ scratch; K2 = R7's exact schedule but prologue = ONE L2-hot
// LDG.128 per thread. Per-CTA loads 20KB -> 4KB, dependency chain gone.

#define MAX_BT 8192
__device__ float g_Y[MAX_BT * 512];          // scratch: precomputed y rows

// ---- Kernel 1: Y[bt, :] = x[bt] @ W^T + b, 8 rows per CTA ----
__global__ __launch_bounds__(128)
void tfe_compute_y_kernel(const float* __restrict__ x,
                          const float* __restrict__ W,
                          const float* __restrict__ b,
                          int BT)
{
    const int d4 = threadIdx.x;              // 0..127, float4 slice of D=512

    const float4 b4 = __ldg(reinterpret_cast<const float4*>(b) + d4);
    const float4* W4 = reinterpret_cast<const float4*>(W);
    const float4 w0 = __ldg(W4 + d4 * 4 + 0);
    const float4 w1 = __ldg(W4 + d4 * 4 + 1);
    const float4 w2 = __ldg(W4 + d4 * 4 + 2);
    const float4 w3 = __ldg(W4 + d4 * 4 + 3);

    float4* Y4 = reinterpret_cast<float4*>(g_Y);
    const int row0 = blockIdx.x * 8;

    #pragma unroll
    for (int r = 0; r < 8; r++) {
        const int bt = row0 + r;
        if (bt >= BT) break;
        const float4 x4 = __ldg(reinterpret_cast<const float4*>(x) + bt);
        float4 y4;
        y4.x = fmaf(x4.x, w0.x, fmaf(x4.y, w0.y, fmaf(x4.z, w0.z, fmaf(x4.w, w0.w, b4.x))));
        y4.y = fmaf(x4.x, w1.x, fmaf(x4.y, w1.y, fmaf(x4.z, w1.z, fmaf(x4.w, w1.w, b4.y))));
        y4.z = fmaf(x4.x, w2.x, fmaf(x4.y, w2.y, fmaf(x4.z, w2.z, fmaf(x4.w, w2.w, b4.z))));
        y4.w = fmaf(x4.x, w3.x, fmaf(x4.y, w3.y, fmaf(x4.z, w3.z, fmaf(x4.w, w3.w, b4.w))));
        Y4[bt * 128 + d4] = y4;              // default cache op: stays L2-hot
    }
}

// ---- Kernel 2: broadcast Y rows S times (R7 schedule, 1-load prologue) ----
__global__ __launch_bounds__(256, 8)
void tfe_broadcast_kernel(float* __restrict__ out, int S, int split_shift)
{
    const int bt   = blockIdx.x >> split_shift;              // (b,t) row
    const int part = blockIdx.x & ((1 << split_shift) - 1);  // slice of repeats
    const int tid  = threadIdx.x;
    const int d4   = tid & 127;

    // Single L2-hot load: this thread's float4 of the precomputed row.
    const float4 y4 = __ldg(reinterpret_cast<const float4*>(g_Y) + bt * 128 + d4);

    // Slice: (S >> split_shift) * 128 float4, contiguous, 256-aligned
    // (launcher guarantees S >> shift is even). (i & 127) == d4 always:
    // one register streamed, warps write 512B contiguous per STG.128.
    const int slice4 = (S >> split_shift) * 128;
    float4* out4 = reinterpret_cast<float4*>(out)
                 + (size_t)bt * (size_t)S * 128u
                 + (size_t)part * (size_t)slice4;

    #pragma unroll 4
    for (int i = tid; i < slice4; i += 256) {
        __stcs(out4 + i, y4);   // evict-first streaming store
    }
}

// ---- Fallback (R7 single-kernel) for BT > MAX_BT ----
__global__ __launch_bounds__(256, 8)
void tfe_fused_kernel(const float* __restrict__ x,
                      const float* __restrict__ W,
                      const float* __restrict__ b,
                      float* __restrict__ out,
                      int S, int split_shift)
{
    const int bt   = blockIdx.x >> split_shift;
    const int part = blockIdx.x & ((1 << split_shift) - 1);
    const int tid  = threadIdx.x;
    const int d4   = tid & 127;

    const float4 x4 = __ldg(reinterpret_cast<const float4*>(x) + bt);
    const float4 b4 = __ldg(reinterpret_cast<const float4*>(b) + d4);
    const float4* W4 = reinterpret_cast<const float4*>(W);
    const float4 w0 = __ldg(W4 + d4 * 4 + 0);
    const float4 w1 = __ldg(W4 + d4 * 4 + 1);
    const float4 w2 = __ldg(W4 + d4 * 4 + 2);
    const float4 w3 = __ldg(W4 + d4 * 4 + 3);

    float4 y4;
    y4.x = fmaf(x4.x, w0.x, fmaf(x4.y, w0.y, fmaf(x4.z, w0.z, fmaf(x4.w, w0.w, b4.x))));
    y4.y = fmaf(x4.x, w1.x, fmaf(x4.y, w1.y, fmaf(x4.z, w1.z, fmaf(x4.w, w1.w, b4.y))));
    y4.z = fmaf(x4.x, w2.x, fmaf(x4.y, w2.y, fmaf(x4.z, w2.z, fmaf(x4.w, w2.w, b4.z))));
    y4.w = fmaf(x4.x, w3.x, fmaf(x4.y, w3.y, fmaf(x4.z, w3.z, fmaf(x4.w, w3.w, b4.w))));

    const int slice4 = (S >> split_shift) * 128;
    float4* out4 = reinterpret_cast<float4*>(out)
                 + (size_t)bt * (size_t)S * 128u
                 + (size_t)part * (size_t)slice4;

    #pragma unroll 4
    for (int i = tid; i < slice4; i += 256) {
        __stcs(out4 + i, y4);
    }
}

extern "C" void kernel_launch(void* const* d_in, const int* in_sizes, int n_in,
                              void* d_out, int out_size)
{
    // Inputs: x [B,T,4] f32, S (scalar), W [512,4] f32, b [512] f32.
    const float* x = (const float*)d_in[0];
    const float* W = (const float*)d_in[2];
    const float* b = (const float*)d_in[3];
    float* out = (float*)d_out;

    const int BT = in_sizes[0] / 4;          // B*T rows (d_inp = 4)
    const int S  = out_size / (BT * 512);    // recover S arithmetically

    // Largest split_shift in {2,1,0} with S >> shift even (preserves the
    // 256-float4 alignment invariant). S=64 -> shift=2 (split=4), grid 12288.
    int shift = 0;
    if      ((S % 8) == 0) shift = 2;
    else if ((S % 4) == 0) shift = 1;

    if (BT <= MAX_BT) {
        tfe_compute_y_kernel<<<(BT + 7) / 8, 128>>>(x, W, b, BT);
        tfe_broadcast_kernel<<<BT << shift, 256>>>(out, S, shift);
    } else {
        tfe_fused_kernel<<<BT << shift, 256>>>(x, W, b, out, S, shift);
    }
}

// round 12
// speedup vs baseline: 1.3052x; 1.0485x over previous
#include <cuda_runtime.h>
#include <cuda_bf16.h>

// TimeFeatureEmbedding: y = x @ W^T + b  ([B,T,4] x [512,4] -> [B,T,512]),
// broadcast each (b,t) row S times -> [B,T,S,512].  402.7 MB pure store stream.
//
// CONVERGED CONFIG (R7): grid = BT*4 (split=4), 256 threads, 8 STG.128/thread
// of one register-resident float4, __stcs streaming stores, warp-contiguous
// 512B per store. Sustains 7.17 TB/s effective writes (~90% of HBM3e spec).
//
// Probed and rejected: persistent CTAs (straggler-bound, 68us), split=8 in
// both 256t/128t shapes (prologue exposure, 75.8/62.2us), two-phase
// precompute-Y (prologue loads were never the limiter, 60.9us). split=4 is
// the drain-granularity optimum of the family.

__global__ __launch_bounds__(256, 8)
void tfe_broadcast_kernel(const float* __restrict__ x,
                          const float* __restrict__ W,
                          const float* __restrict__ b,
                          float* __restrict__ out,
                          int S, int split_shift)
{
    const int bt   = blockIdx.x >> split_shift;              // (b,t) row
    const int part = blockIdx.x & ((1 << split_shift) - 1);  // slice of S repeats
    const int tid  = threadIdx.x;
    const int d4   = tid & 127;              // float4 index within D_MODEL=512

    // x row: 4 floats broadcast across the CTA (L1/L2-hot after first wave)
    const float4 x4 = __ldg(reinterpret_cast<const float4*>(x) + bt);

    // bias + W slice for this thread's 4 output dims
    const float4 b4 = __ldg(reinterpret_cast<const float4*>(b) + d4);
    const float4* W4 = reinterpret_cast<const float4*>(W);
    const float4 w0 = __ldg(W4 + d4 * 4 + 0);
    const float4 w1 = __ldg(W4 + d4 * 4 + 1);
    const float4 w2 = __ldg(W4 + d4 * 4 + 2);
    const float4 w3 = __ldg(W4 + d4 * 4 + 3);

    float4 y4;
    y4.x = fmaf(x4.x, w0.x, fmaf(x4.y, w0.y, fmaf(x4.z, w0.z, fmaf(x4.w, w0.w, b4.x))));
    y4.y = fmaf(x4.x, w1.x, fmaf(x4.y, w1.y, fmaf(x4.z, w1.z, fmaf(x4.w, w1.w, b4.y))));
    y4.z = fmaf(x4.x, w2.x, fmaf(x4.y, w2.y, fmaf(x4.z, w2.z, fmaf(x4.w, w2.w, b4.z))));
    y4.w = fmaf(x4.x, w3.x, fmaf(x4.y, w3.y, fmaf(x4.z, w3.z, fmaf(x4.w, w3.w, b4.w))));

    // Slice: (S >> split_shift) * 128 float4, contiguous, 256-aligned start
    // (launcher guarantees S >> shift is even -> slice length multiple of
    // 256). Hence (i & 127) == d4 on every iteration: the same register-
    // resident float4 is streamed; each warp store is 512B contiguous.
    const int slice4 = (S >> split_shift) * 128;
    float4* out4 = reinterpret_cast<float4*>(out)
                 + (size_t)bt * (size_t)S * 128u
                 + (size_t)part * (size_t)slice4;

    #pragma unroll 4
    for (int i = tid; i < slice4; i += 256) {
        __stcs(out4 + i, y4);   // evict-first streaming store
    }
}

extern "C" void kernel_launch(void* const* d_in, const int* in_sizes, int n_in,
                              void* d_out, int out_size)
{
    // Inputs: x [B,T,4] f32, S (scalar), W [512,4] f32, b [512] f32.
    const float* x = (const float*)d_in[0];
    const float* W = (const float*)d_in[2];
    const float* b = (const float*)d_in[3];
    float* out = (float*)d_out;

    const int BT = in_sizes[0] / 4;          // B*T rows (d_inp = 4)
    const int S  = out_size / (BT * 512);    // recover S arithmetically

    // split=4 when S/4 is even (preserves the 256-float4 alignment
    // invariant); degrade gracefully otherwise. S=64 -> shift=2, grid 12288.
    int shift = 0;
    if      ((S % 8) == 0) shift = 2;
    else if ((S % 4) == 0) shift = 1;

    tfe_broadcast_kernel<<<BT << shift, 256>>>(x, W, b, out, S, shift);
}